// round 8
// baseline (speedup 1.0000x reference)
#include <cuda_runtime.h>
#include <cuda_bf16.h>

// img : (1, 64, 64, 1024) float32, NHWC
// rois: (1, 512, 4) int32  -> (x, y, w, h)
// out : (1, 512, 7, 7, 1024) float32
#define POOL   7
#define NROIS  512
#define IMG_W  64

// ---- packed f32x2 helpers (sm_103a) ----
__device__ __forceinline__ unsigned long long pk(float v) {
    unsigned long long r;
    asm("mov.b64 %0, {%1, %1};" : "=l"(r) : "f"(v));
    return r;
}
__device__ __forceinline__ unsigned long long mul2(unsigned long long a, unsigned long long b) {
    unsigned long long r;
    asm("mul.rn.f32x2 %0, %1, %2;" : "=l"(r) : "l"(a), "l"(b));
    return r;
}
__device__ __forceinline__ unsigned long long fma2(unsigned long long a, unsigned long long b,
                                                   unsigned long long c) {
    unsigned long long r;
    asm("fma.rn.f32x2 %0, %1, %2, %3;" : "=l"(r) : "l"(a), "l"(b), "l"(c));
    return r;
}

// 16B img load, non-coherent, keep resident in L1 (reused across px).
__device__ __forceinline__ ulonglong2 ldg_el(const ulonglong2* p) {
    ulonglong2 v;
    asm("ld.global.nc.L1::evict_last.v2.b64 {%0, %1}, [%2];"
        : "=l"(v.x), "=l"(v.y) : "l"(p));
    return v;
}
// 16B streaming store (output never re-read).
__device__ __forceinline__ void stg_cs(ulonglong2* p, ulonglong2 v) {
    asm volatile("st.global.cs.v2.b64 [%0], {%1, %2};"
                 :: "l"(p), "l"(v.x), "l"(v.y) : "memory");
}

__device__ __forceinline__ ulonglong2 blend2(ulonglong2 v00, ulonglong2 v01,
                                             ulonglong2 v10, ulonglong2 v11,
                                             float fx, float fy) {
    const float w11 = fx * fy;
    const float w01 = fx - w11;          // fx*(1-fy)
    const float w10 = fy - w11;          // (1-fx)*fy
    const float w00 = 1.0f - fx - w10;   // (1-fx)*(1-fy)
    const unsigned long long W00 = pk(w00), W01 = pk(w01),
                             W10 = pk(w10), W11 = pk(w11);
    ulonglong2 o;
    o.x = fma2(v11.x, W11, fma2(v10.x, W10, fma2(v01.x, W01, mul2(v00.x, W00))));
    o.y = fma2(v11.y, W11, fma2(v10.y, W10, fma2(v01.y, W01, mul2(v00.y, W00))));
    return o;
}

// One CTA per (roi, py) output row: 7 px cells, 256 threads, 1 float4 lane
// each. Depth-2 double-buffered pipeline: blend cell i (loaded 2 iterations
// ago) then issue loads for cell i+2 — the consume distance covers the L2
// round-trip even at 32 warps/SM.
__global__ __launch_bounds__(256, 4)
void roi_pool_kernel(const float* __restrict__ img,
                     const int*   __restrict__ rois,
                     float*       __restrict__ out)
{
    const int bid = blockIdx.x;           // roi*7 + py
    const int roi = bid / POOL;
    const int py  = bid - roi * POOL;

    const int4 r = __ldg(((const int4*)rois) + roi);   // x, y, w, h

    // Loop-invariant y-axis work (match reference fp32 arithmetic exactly)
    const float stepx = (float)r.z / (float)POOL;
    const float sy = (float)py * ((float)r.w / (float)POOL);
    const int   y0 = (int)sy;
    const float fy = sy - (float)y0;
    const int   y1 = min(y0 + 1, r.w - 1);
    const int   wm1 = r.z - 1;

    const int c = threadIdx.x;            // 0..255 float4 lane
    const ulonglong2* ibase = (const ulonglong2*)img;
    const unsigned row0 = (unsigned)((r.y + y0) * IMG_W + r.x) * 256u + c;
    const unsigned row1 = (unsigned)((r.y + y1) * IMG_W + r.x) * 256u + c;

    ulonglong2* optr = (ulonglong2*)out + ((size_t)bid * POOL) * 256 + c;

    // Double-buffered pipeline state (all indices compile-time after unroll).
    ulonglong2 v00[2], v01[2], v10[2], v11[2];
    float      fxb[2];

    // prologue: load cells 0 and 1
    #pragma unroll
    for (int k = 0; k < 2; ++k) {
        const float sx = (float)k * stepx;
        const int   x0 = (int)sx;
        fxb[k] = sx - (float)x0;
        const unsigned u0 = (unsigned)x0 * 256u;
        const unsigned u1 = (unsigned)min(x0 + 1, wm1) * 256u;
        v00[k] = ldg_el(ibase + row0 + u0);
        v01[k] = ldg_el(ibase + row0 + u1);
        v10[k] = ldg_el(ibase + row1 + u0);
        v11[k] = ldg_el(ibase + row1 + u1);
    }

    #pragma unroll
    for (int px = 0; px < POOL; ++px) {
        const int s = px & 1;
        // blend + store cell px (its loads were issued 2 iterations ago)
        stg_cs(optr, blend2(v00[s], v01[s], v10[s], v11[s], fxb[s], fy));
        optr += 256;

        // issue loads for cell px+2 into the buffer just freed
        if (px + 2 < POOL) {
            const float sx = (float)(px + 2) * stepx;
            const int   x0 = (int)sx;
            fxb[s] = sx - (float)x0;
            const unsigned u0 = (unsigned)x0 * 256u;
            const unsigned u1 = (unsigned)min(x0 + 1, wm1) * 256u;
            v00[s] = ldg_el(ibase + row0 + u0);
            v01[s] = ldg_el(ibase + row0 + u1);
            v10[s] = ldg_el(ibase + row1 + u0);
            v11[s] = ldg_el(ibase + row1 + u1);
        }
    }
}

extern "C" void kernel_launch(void* const* d_in, const int* in_sizes, int n_in,
                              void* d_out, int out_size)
{
    const float* img  = (const float*)d_in[0];
    const int*   rois = (const int*)d_in[1];
    float*       out  = (float*)d_out;

    const int grid = NROIS * POOL;        // 3584 CTAs, one per (roi, py)
    roi_pool_kernel<<<grid, 256>>>(img, rois, out);
}